// round 3
// baseline (speedup 1.0000x reference)
#include <cuda_runtime.h>
#include <cuda_bf16.h>

// Problem constants (N=170000, E=1200000, IN=HID=128, OUT=40)
#define NN 170000
#define EE 1200000
#define CIN 128
#define CH 128
#define COUT 40

// Scratch (static __device__ arrays per allocation rules)
__device__ float g_h1[(size_t)NN * CH];    // x @ W1
__device__ float g_agg1[(size_t)NN * CH];  // edge-aggregated h1, then relu'd h
__device__ float g_h2[(size_t)NN * COUT];  // h @ W2
__device__ float g_deg[NN];
__device__ float g_dis[NN];

// ---------------------------------------------------------------------------
// init: zero agg1 and d_out, set deg = 1 (self-loop)
__global__ void k_init(float* __restrict__ out, int n) {
    int idx = blockIdx.x * blockDim.x + threadIdx.x;
    if (idx < n * CH) g_agg1[idx] = 0.f;
    if (idx < n * COUT) out[idx] = 0.f;
    if (idx < n) g_deg[idx] = 1.0f;
}

// deg accumulation over edges (dst side)
__global__ void k_deg(const int* __restrict__ dst, int e) {
    int idx = blockIdx.x * blockDim.x + threadIdx.x;
    if (idx < e) atomicAdd(&g_deg[dst[idx]], 1.0f);
}

__global__ void k_dis(int n) {
    int idx = blockIdx.x * blockDim.x + threadIdx.x;
    if (idx < n) g_dis[idx] = rsqrtf(g_deg[idx]);
}

// ---------------------------------------------------------------------------
// Register-tiled fp32 GEMM: Y[n, wcols] = X[n,128] @ W[128, wcols]
// W held in smem padded to CO cols; X tile of ROWS rows in smem.
// 256 threads; each thread computes 4 cols x RPT rows.
template <int CO, int ROWS>
__global__ void k_gemm(const float* __restrict__ X, const float* __restrict__ Wg,
                       int wcols, float* __restrict__ Y, int n) {
    extern __shared__ float sm[];
    float* Ws = sm;              // 128*CO
    float* Xs = sm + 128 * CO;   // ROWS*128
    const int t = threadIdx.x;

    for (int idx = t; idx < 128 * CO; idx += 256) {
        int k = idx / CO, j = idx % CO;
        Ws[idx] = (j < wcols) ? Wg[k * wcols + j] : 0.f;
    }
    const int row0 = blockIdx.x * ROWS;
    const int XT = ROWS * 32;  // float4 count
    for (int idx = t; idx < XT; idx += 256) {
        int r = idx >> 5, c = idx & 31;
        float4 v = make_float4(0.f, 0.f, 0.f, 0.f);
        if (row0 + r < n) v = ((const float4*)(X + (size_t)(row0 + r) * 128))[c];
        ((float4*)Xs)[idx] = v;
    }
    __syncthreads();

    constexpr int CG = CO / 4;            // column groups
    constexpr int RPT = ROWS / (256 / CG);
    const int jb = (t % CG) * 4;
    const int rb = (t / CG) * RPT;

    float acc[RPT][4];
#pragma unroll
    for (int r = 0; r < RPT; r++) {
        acc[r][0] = 0.f; acc[r][1] = 0.f; acc[r][2] = 0.f; acc[r][3] = 0.f;
    }

#pragma unroll 8
    for (int k = 0; k < 128; k++) {
        float4 w = *(const float4*)(Ws + k * CO + jb);
#pragma unroll
        for (int r = 0; r < RPT; r++) {
            float xv = Xs[(rb + r) * 128 + k];
            acc[r][0] = fmaf(xv, w.x, acc[r][0]);
            acc[r][1] = fmaf(xv, w.y, acc[r][1]);
            acc[r][2] = fmaf(xv, w.z, acc[r][2]);
            acc[r][3] = fmaf(xv, w.w, acc[r][3]);
        }
    }

#pragma unroll
    for (int r = 0; r < RPT; r++) {
        int row = row0 + rb + r;
        if (row >= n) continue;
        if (CO == wcols) {
            float4 v = make_float4(acc[r][0], acc[r][1], acc[r][2], acc[r][3]);
            *(float4*)(Y + (size_t)row * wcols + jb) = v;
        } else {
#pragma unroll
            for (int i = 0; i < 4; i++)
                if (jb + i < wcols) Y[(size_t)row * wcols + jb + i] = acc[r][i];
        }
    }
}

// ---------------------------------------------------------------------------
// Edge aggregation, 128 channels: one warp per edge, float4 gather + 4 REDs/lane
__global__ void k_agg128(const int* __restrict__ src, const int* __restrict__ dst, int e) {
    int g = blockIdx.x * blockDim.x + threadIdx.x;
    int ed = g >> 5, lane = g & 31;
    if (ed >= e) return;
    int s = src[ed], d = dst[ed];
    float norm = g_dis[s] * g_dis[d];
    float4 v = ((const float4*)(g_h1 + (size_t)s * CH))[lane];
    float* o = g_agg1 + (size_t)d * CH + lane * 4;
    atomicAdd(o + 0, v.x * norm);
    atomicAdd(o + 1, v.y * norm);
    atomicAdd(o + 2, v.z * norm);
    atomicAdd(o + 3, v.w * norm);
}

// self-loop + bias + relu, in place on agg1 (becomes layer-2 input h)
__global__ void k_relu_bias(const float* __restrict__ b1, int n) {
    int idx = blockIdx.x * blockDim.x + threadIdx.x;
    if (idx >= n * CH) return;
    int i = idx >> 7, c = idx & 127;
    float di = g_dis[i];
    float v = g_agg1[idx] + g_h1[idx] * di * di + b1[c];
    g_agg1[idx] = fmaxf(v, 0.f);
}

// Edge aggregation, 40 channels into d_out: 8 threads/edge, 5 channels each
__global__ void k_agg40(const int* __restrict__ src, const int* __restrict__ dst,
                        float* __restrict__ out, int e) {
    int g = blockIdx.x * blockDim.x + threadIdx.x;
    int ed = g >> 3, l = g & 7;
    if (ed >= e) return;
    int s = src[ed], d = dst[ed];
    float norm = g_dis[s] * g_dis[d];
    const float* hv = g_h2 + (size_t)s * COUT + l * 5;
    float* o = out + (size_t)d * COUT + l * 5;
#pragma unroll
    for (int i = 0; i < 5; i++) atomicAdd(o + i, hv[i] * norm);
}

// final: out += h2 * dis^2 + b2
__global__ void k_final(const float* __restrict__ b2, float* __restrict__ out, int n) {
    int idx = blockIdx.x * blockDim.x + threadIdx.x;
    if (idx >= n * COUT) return;
    int i = idx / COUT, c = idx % COUT;
    float di = g_dis[i];
    out[idx] += g_h2[idx] * di * di + b2[c];
}

// ---------------------------------------------------------------------------
extern "C" void kernel_launch(void* const* d_in, const int* in_sizes, int n_in,
                              void* d_out, int out_size) {
    const float* x  = (const float*)d_in[0];
    const float* W1 = (const float*)d_in[1];
    const float* b1 = (const float*)d_in[2];
    const float* W2 = (const float*)d_in[3];
    const float* b2 = (const float*)d_in[4];
    const int* edge = (const int*)d_in[5];

    const int n = in_sizes[0] / CIN;
    const int e = in_sizes[5] / 2;
    const int* src = edge;
    const int* dst = edge + e;
    float* out = (float*)d_out;

    // Resolve device-global scratch addresses (host-side query; capture-safe,
    // no allocation, deterministic).
    float *p_h1 = nullptr, *p_agg1 = nullptr, *p_h2 = nullptr;
    cudaGetSymbolAddress((void**)&p_h1, g_h1);
    cudaGetSymbolAddress((void**)&p_agg1, g_agg1);
    cudaGetSymbolAddress((void**)&p_h2, g_h2);

    const int smem = (128 * 128 + 128 * 128) * sizeof(float);  // 128 KB (covers both)
    cudaFuncSetAttribute(k_gemm<128, 64>, cudaFuncAttributeMaxDynamicSharedMemorySize, smem);
    cudaFuncSetAttribute(k_gemm<64, 128>, cudaFuncAttributeMaxDynamicSharedMemorySize, smem);

    // degree / normalization
    k_init<<<(n * CH + 255) / 256, 256>>>(out, n);
    k_deg<<<(e + 255) / 256, 256>>>(dst, e);
    k_dis<<<(n + 255) / 256, 256>>>(n);

    // layer 1
    k_gemm<128, 64><<<(n + 63) / 64, 256, smem>>>(x, W1, 128, p_h1, n);
    k_agg128<<<(int)(((size_t)e * 32 + 255) / 256), 256>>>(src, dst, e);
    k_relu_bias<<<(n * CH + 255) / 256, 256>>>(b1, n);

    // layer 2 (GEMM first: aggregate only 40 channels)
    k_gemm<64, 128><<<(n + 127) / 128, 256, smem>>>(p_agg1, W2, COUT, p_h2, n);
    k_agg40<<<(int)(((size_t)e * 8 + 255) / 256), 256>>>(src, dst, out, e);
    k_final<<<(n * COUT + 255) / 256, 256>>>(b2, out, n);
}

// round 4
// speedup vs baseline: 1.7191x; 1.7191x over previous
#include <cuda_runtime.h>
#include <cuda_bf16.h>

// Problem constants (N=170000, E=1200000, IN=HID=128, OUT=40)
#define NN 170000
#define EE 1200000
#define CIN 128
#define CH 128
#define COUT 40

// Scratch (static __device__ arrays per allocation rules)
__device__ float g_h1s[(size_t)NN * CH];    // dis * (x @ W1)
__device__ float g_agg1[(size_t)NN * CH];   // edge-aggregated h1s, then relu'd h
__device__ float g_h2s[(size_t)NN * COUT];  // dis * (h @ W2)
__device__ float g_deg[NN];
__device__ float g_dis[NN];

// ---------------------------------------------------------------------------
// init: zero agg1 and d_out (float4), set deg = 1 (self-loop)
__global__ void k_init(float4* __restrict__ out, int n) {
    int idx = blockIdx.x * blockDim.x + threadIdx.x;
    const float4 z = make_float4(0.f, 0.f, 0.f, 0.f);
    if (idx < n * (CH / 4)) ((float4*)g_agg1)[idx] = z;
    if (idx < n * (COUT / 4)) out[idx] = z;
    if (idx < n) g_deg[idx] = 1.0f;
}

__global__ void k_deg(const int* __restrict__ dst, int e) {
    int idx = blockIdx.x * blockDim.x + threadIdx.x;
    if (idx < e) atomicAdd(&g_deg[dst[idx]], 1.0f);
}

__global__ void k_dis(int n) {
    int idx = blockIdx.x * blockDim.x + threadIdx.x;
    if (idx < n) g_dis[idx] = rsqrtf(g_deg[idx]);
}

// ---------------------------------------------------------------------------
// Register-tiled fp32 GEMM with epilogue row-scale by g_dis:
//   Y[row, :] = dis[row] * (X[row,:128] @ W[:128, wcols])
template <int CO, int ROWS>
__global__ void k_gemm(const float* __restrict__ X, const float* __restrict__ Wg,
                       int wcols, float* __restrict__ Y, int n) {
    extern __shared__ float sm[];
    float* Ws = sm;              // 128*CO
    float* Xs = sm + 128 * CO;   // ROWS*128
    const int t = threadIdx.x;

    for (int idx = t; idx < 128 * CO; idx += 256) {
        int k = idx / CO, j = idx % CO;
        Ws[idx] = (j < wcols) ? Wg[k * wcols + j] : 0.f;
    }
    const int row0 = blockIdx.x * ROWS;
    const int XT = ROWS * 32;  // float4 count
    for (int idx = t; idx < XT; idx += 256) {
        int r = idx >> 5, c = idx & 31;
        float4 v = make_float4(0.f, 0.f, 0.f, 0.f);
        if (row0 + r < n) v = ((const float4*)(X + (size_t)(row0 + r) * 128))[c];
        ((float4*)Xs)[idx] = v;
    }
    __syncthreads();

    constexpr int CG = CO / 4;            // column groups
    constexpr int RPT = ROWS / (256 / CG);
    const int jb = (t % CG) * 4;
    const int rb = (t / CG) * RPT;

    float acc[RPT][4];
#pragma unroll
    for (int r = 0; r < RPT; r++) {
        acc[r][0] = 0.f; acc[r][1] = 0.f; acc[r][2] = 0.f; acc[r][3] = 0.f;
    }

#pragma unroll 8
    for (int k = 0; k < 128; k++) {
        float4 w = *(const float4*)(Ws + k * CO + jb);
#pragma unroll
        for (int r = 0; r < RPT; r++) {
            float xv = Xs[(rb + r) * 128 + k];
            acc[r][0] = fmaf(xv, w.x, acc[r][0]);
            acc[r][1] = fmaf(xv, w.y, acc[r][1]);
            acc[r][2] = fmaf(xv, w.z, acc[r][2]);
            acc[r][3] = fmaf(xv, w.w, acc[r][3]);
        }
    }

#pragma unroll
    for (int r = 0; r < RPT; r++) {
        int row = row0 + rb + r;
        if (row >= n) continue;
        float di = g_dis[row];
        if (CO == wcols) {
            float4 v = make_float4(acc[r][0] * di, acc[r][1] * di,
                                   acc[r][2] * di, acc[r][3] * di);
            *(float4*)(Y + (size_t)row * wcols + jb) = v;
        } else {
#pragma unroll
            for (int i = 0; i < 4; i++)
                if (jb + i < wcols) Y[(size_t)row * wcols + jb + i] = acc[r][i] * di;
        }
    }
}

// ---------------------------------------------------------------------------
// Edge aggregation, 128 channels: warp/edge, float4 gather + vector RED.128
__global__ void k_agg128(const int* __restrict__ src, const int* __restrict__ dst, int e) {
    int g = blockIdx.x * blockDim.x + threadIdx.x;
    int ed = g >> 5, lane = g & 31;
    if (ed >= e) return;
    int s = src[ed], d = dst[ed];
    float4 v = ((const float4*)(g_h1s + (size_t)s * CH))[lane];
    float* o = g_agg1 + (size_t)d * CH + lane * 4;
    asm volatile("red.global.add.v4.f32 [%0], {%1,%2,%3,%4};"
                 :: "l"(o), "f"(v.x), "f"(v.y), "f"(v.z), "f"(v.w) : "memory");
}

// h = relu(dis*(agg + h1s) + b1), in place on agg1; float4 over n*32
__global__ void k_relu_bias(const float* __restrict__ b1, int n) {
    int idx = blockIdx.x * blockDim.x + threadIdx.x;
    if (idx >= n * 32) return;
    int i = idx >> 5, c = idx & 31;
    float di = g_dis[i];
    float4 a = ((const float4*)g_agg1)[idx];
    float4 h = ((const float4*)g_h1s)[idx];
    float4 b = ((const float4*)b1)[c];
    float4 r;
    r.x = fmaxf(fmaf(di, a.x + h.x, b.x), 0.f);
    r.y = fmaxf(fmaf(di, a.y + h.y, b.y), 0.f);
    r.z = fmaxf(fmaf(di, a.z + h.z, b.z), 0.f);
    r.w = fmaxf(fmaf(di, a.w + h.w, b.w), 0.f);
    ((float4*)g_agg1)[idx] = r;
}

// Edge aggregation, 40 channels into d_out: 10 threads/edge x 4ch, RED.128
__global__ void k_agg40(const int* __restrict__ src, const int* __restrict__ dst,
                        float* __restrict__ out, int e) {
    int g = blockIdx.x * blockDim.x + threadIdx.x;
    int ed = g / 10, l = g % 10;
    if (ed >= e) return;
    int s = src[ed], d = dst[ed];
    float4 v = *(const float4*)(g_h2s + (size_t)s * COUT + l * 4);
    float* o = out + (size_t)d * COUT + l * 4;
    asm volatile("red.global.add.v4.f32 [%0], {%1,%2,%3,%4};"
                 :: "l"(o), "f"(v.x), "f"(v.y), "f"(v.z), "f"(v.w) : "memory");
}

// final: out = dis*(out + h2s) + b2; float4 over n*10
__global__ void k_final(const float* __restrict__ b2, float* __restrict__ out, int n) {
    int idx = blockIdx.x * blockDim.x + threadIdx.x;
    if (idx >= n * 10) return;
    int i = idx / 10, c = idx % 10;
    float di = g_dis[i];
    float4 a = ((const float4*)out)[idx];
    float4 h = ((const float4*)g_h2s)[idx];
    float4 b = ((const float4*)b2)[c];
    float4 r;
    r.x = fmaf(di, a.x + h.x, b.x);
    r.y = fmaf(di, a.y + h.y, b.y);
    r.z = fmaf(di, a.z + h.z, b.z);
    r.w = fmaf(di, a.w + h.w, b.w);
    ((float4*)out)[idx] = r;
}

// ---------------------------------------------------------------------------
extern "C" void kernel_launch(void* const* d_in, const int* in_sizes, int n_in,
                              void* d_out, int out_size) {
    const float* x  = (const float*)d_in[0];
    const float* W1 = (const float*)d_in[1];
    const float* b1 = (const float*)d_in[2];
    const float* W2 = (const float*)d_in[3];
    const float* b2 = (const float*)d_in[4];
    const int* edge = (const int*)d_in[5];

    const int n = in_sizes[0] / CIN;
    const int e = in_sizes[5] / 2;
    const int* src = edge;
    const int* dst = edge + e;
    float* out = (float*)d_out;

    float *p_h1s = nullptr, *p_agg1 = nullptr, *p_h2s = nullptr;
    cudaGetSymbolAddress((void**)&p_h1s, g_h1s);
    cudaGetSymbolAddress((void**)&p_agg1, g_agg1);
    cudaGetSymbolAddress((void**)&p_h2s, g_h2s);

    // Exact smem request: 96 KB each -> 2 CTAs/SM (was 128 KB -> 1 CTA/SM)
    const int smem1 = (128 * 128 + 64 * 128) * sizeof(float);   // 96 KB
    const int smem2 = (128 * 64 + 128 * 128) * sizeof(float);   // 96 KB
    cudaFuncSetAttribute(k_gemm<128, 64>, cudaFuncAttributeMaxDynamicSharedMemorySize, smem1);
    cudaFuncSetAttribute(k_gemm<64, 128>, cudaFuncAttributeMaxDynamicSharedMemorySize, smem2);

    // degree / normalization
    k_init<<<(n * CH / 4 + 255) / 256, 256>>>((float4*)out, n);
    k_deg<<<(e + 255) / 256, 256>>>(dst, e);
    k_dis<<<(n + 255) / 256, 256>>>(n);

    // layer 1
    k_gemm<128, 64><<<(n + 63) / 64, 256, smem1>>>(x, W1, 128, p_h1s, n);
    k_agg128<<<(int)(((size_t)e * 32 + 255) / 256), 256>>>(src, dst, e);
    k_relu_bias<<<(n * 32 + 255) / 256, 256>>>(b1, n);

    // layer 2 (GEMM first: aggregate only 40 channels)
    k_gemm<64, 128><<<(n + 127) / 128, 256, smem2>>>(p_agg1, W2, COUT, p_h2s, n);
    k_agg40<<<(int)(((size_t)e * 10 + 319) / 320), 320>>>(src, dst, out, e);
    k_final<<<(n * 10 + 255) / 256, 256>>>(b2, out, n);
}

// round 5
// speedup vs baseline: 2.0241x; 1.1774x over previous
#include <cuda_runtime.h>
#include <cuda_bf16.h>

// Problem constants (N=170000, E=1200000, IN=HID=128, OUT=40)
#define NN 170000
#define EE 1200000
#define CIN 128
#define CH 128
#define COUT 40
#define SCAN_B 512
#define NBLK ((NN + SCAN_B - 1) / SCAN_B)   // 333

// Scratch (static __device__ arrays per allocation rules)
__device__ float g_h1s[(size_t)NN * CH];    // dis * (x @ W1)
__device__ float g_h[(size_t)NN * CH];      // relu'd hidden (layer-2 input)
__device__ float g_h2s[(size_t)NN * COUT];  // dis * (h @ W2)
__device__ float g_dis[NN];
__device__ int g_cnt[NN];    // in-degree histogram (excl. self-loop)
__device__ int g_incl[NN];   // inclusive prefix sum of g_cnt
__device__ int g_cur[NN];    // scatter cursor
__device__ int g_bsum[NBLK];
__device__ int g_boff[NBLK];
__device__ int g_csrc[EE];   // edge srcs grouped by dst

// ---------------------------------------------------------------------------
// CSR build: zero, histogram, 2-level scan, scatter
__global__ void k_zero(int n) {
    int i = blockIdx.x * blockDim.x + threadIdx.x;
    if (i < n) { g_cnt[i] = 0; g_cur[i] = 0; }
}

__global__ void k_hist(const int* __restrict__ dst, int e) {
    int i = blockIdx.x * blockDim.x + threadIdx.x;
    if (i < e) atomicAdd(&g_cnt[dst[i]], 1);
}

__global__ void k_scan1(int n) {
    __shared__ int sm[SCAN_B];
    int t = threadIdx.x;
    int i = blockIdx.x * SCAN_B + t;
    int v = (i < n) ? g_cnt[i] : 0;
    sm[t] = v;
    __syncthreads();
#pragma unroll
    for (int off = 1; off < SCAN_B; off <<= 1) {
        int u = (t >= off) ? sm[t - off] : 0;
        __syncthreads();
        sm[t] += u;
        __syncthreads();
    }
    if (i < n) g_incl[i] = sm[t];
    if (t == SCAN_B - 1) g_bsum[blockIdx.x] = sm[t];
}

__global__ void k_scan2(int nblk) {
    __shared__ int sm[SCAN_B];
    int t = threadIdx.x;
    int v = (t < nblk) ? g_bsum[t] : 0;
    sm[t] = v;
    __syncthreads();
#pragma unroll
    for (int off = 1; off < SCAN_B; off <<= 1) {
        int u = (t >= off) ? sm[t - off] : 0;
        __syncthreads();
        sm[t] += u;
        __syncthreads();
    }
    if (t < nblk) g_boff[t] = sm[t] - v;  // exclusive
}

__global__ void k_scan3(int n) {
    int i = blockIdx.x * SCAN_B + threadIdx.x;
    if (i < n) g_incl[i] += g_boff[blockIdx.x];
}

__global__ void k_dis(int n) {
    int i = blockIdx.x * blockDim.x + threadIdx.x;
    if (i < n) g_dis[i] = rsqrtf((float)(g_cnt[i] + 1));  // +1 self-loop
}

__global__ void k_scatter(const int* __restrict__ src, const int* __restrict__ dst, int e) {
    int i = blockIdx.x * blockDim.x + threadIdx.x;
    if (i >= e) return;
    int d = dst[i];
    int pos = atomicAdd(&g_cur[d], 1);
    g_csrc[g_incl[d] - g_cnt[d] + pos] = src[i];
}

// ---------------------------------------------------------------------------
// 8x8 register-tiled fp32 GEMM, epilogue scales row by g_dis:
//   Y[row,:] = dis[row] * (X[row,:128] @ W[:128, wcols])
// NT = (ROWS/8)*(CO/8) threads.
template <int CO, int ROWS, int NT>
__global__ void __launch_bounds__(NT, 2)
k_gemm8(const float* __restrict__ X, const float* __restrict__ Wg,
        int wcols, float* __restrict__ Y, int n) {
    extern __shared__ float sm[];
    float* Ws = sm;              // 128*CO
    float* Xs = sm + 128 * CO;   // ROWS*128
    const int t = threadIdx.x;

    for (int idx = t; idx < 128 * CO; idx += NT) {
        int k = idx / CO, j = idx % CO;
        Ws[idx] = (j < wcols) ? Wg[k * wcols + j] : 0.f;
    }
    const int row0 = blockIdx.x * ROWS;
    for (int idx = t; idx < ROWS * 32; idx += NT) {
        int r = idx >> 5, c = idx & 31;
        float4 v = make_float4(0.f, 0.f, 0.f, 0.f);
        if (row0 + r < n) v = ((const float4*)(X + (size_t)(row0 + r) * 128))[c];
        ((float4*)Xs)[idx] = v;
    }
    __syncthreads();

    constexpr int CG = CO / 8;
    const int jb = (t % CG) * 8;
    const int rb = (t / CG) * 8;

    float acc[8][8];
#pragma unroll
    for (int r = 0; r < 8; r++)
#pragma unroll
        for (int c = 0; c < 8; c++) acc[r][c] = 0.f;

#pragma unroll 2
    for (int k = 0; k < 128; k++) {
        float4 w0 = *(const float4*)(Ws + k * CO + jb);
        float4 w1 = *(const float4*)(Ws + k * CO + jb + 4);
        float xv[8];
#pragma unroll
        for (int r = 0; r < 8; r++) xv[r] = Xs[(rb + r) * 128 + k];
#pragma unroll
        for (int r = 0; r < 8; r++) {
            acc[r][0] = fmaf(xv[r], w0.x, acc[r][0]);
            acc[r][1] = fmaf(xv[r], w0.y, acc[r][1]);
            acc[r][2] = fmaf(xv[r], w0.z, acc[r][2]);
            acc[r][3] = fmaf(xv[r], w0.w, acc[r][3]);
            acc[r][4] = fmaf(xv[r], w1.x, acc[r][4]);
            acc[r][5] = fmaf(xv[r], w1.y, acc[r][5]);
            acc[r][6] = fmaf(xv[r], w1.z, acc[r][6]);
            acc[r][7] = fmaf(xv[r], w1.w, acc[r][7]);
        }
    }

#pragma unroll
    for (int r = 0; r < 8; r++) {
        int row = row0 + rb + r;
        if (row >= n) continue;
        float di = g_dis[row];
        if (CO == wcols) {
            float4 v0 = make_float4(acc[r][0] * di, acc[r][1] * di, acc[r][2] * di, acc[r][3] * di);
            float4 v1 = make_float4(acc[r][4] * di, acc[r][5] * di, acc[r][6] * di, acc[r][7] * di);
            *(float4*)(Y + (size_t)row * wcols + jb) = v0;
            *(float4*)(Y + (size_t)row * wcols + jb + 4) = v1;
        } else {
#pragma unroll
            for (int c = 0; c < 8; c++)
                if (jb + c < wcols) Y[(size_t)row * wcols + jb + c] = acc[r][c] * di;
        }
    }
}

// ---------------------------------------------------------------------------
// Layer-1 aggregation, CSR gather, fused self-loop+bias+relu. Warp per node.
__global__ void k_aggA(const float* __restrict__ b1, int n) {
    int g = blockIdx.x * blockDim.x + threadIdx.x;
    int node = g >> 5, lane = g & 31;
    if (node >= n) return;
    int end = g_incl[node];
    int p = end - g_cnt[node];
    float4 acc = make_float4(0.f, 0.f, 0.f, 0.f);
    for (; p < end; ++p) {
        int s = g_csrc[p];
        float4 v = ((const float4*)(g_h1s + (size_t)s * CH))[lane];
        acc.x += v.x; acc.y += v.y; acc.z += v.z; acc.w += v.w;
    }
    float4 hs = ((const float4*)(g_h1s + (size_t)node * CH))[lane];
    acc.x += hs.x; acc.y += hs.y; acc.z += hs.z; acc.w += hs.w;
    float di = g_dis[node];
    float4 b = ((const float4*)b1)[lane];
    float4 r;
    r.x = fmaxf(fmaf(di, acc.x, b.x), 0.f);
    r.y = fmaxf(fmaf(di, acc.y, b.y), 0.f);
    r.z = fmaxf(fmaf(di, acc.z, b.z), 0.f);
    r.w = fmaxf(fmaf(di, acc.w, b.w), 0.f);
    ((float4*)(g_h + (size_t)node * CH))[lane] = r;
}

// Layer-2 aggregation, CSR gather, fused self-loop+bias. 10 threads/node x 4ch.
__global__ void k_aggB(const float* __restrict__ b2, float* __restrict__ out, int n) {
    int g = blockIdx.x * blockDim.x + threadIdx.x;
    int node = g / 10, l = g % 10;
    if (node >= n) return;
    int end = g_incl[node];
    int p = end - g_cnt[node];
    float4 acc = make_float4(0.f, 0.f, 0.f, 0.f);
    for (; p < end; ++p) {
        int s = g_csrc[p];
        float4 v = *(const float4*)(g_h2s + (size_t)s * COUT + l * 4);
        acc.x += v.x; acc.y += v.y; acc.z += v.z; acc.w += v.w;
    }
    float4 hs = *(const float4*)(g_h2s + (size_t)node * COUT + l * 4);
    acc.x += hs.x; acc.y += hs.y; acc.z += hs.z; acc.w += hs.w;
    float di = g_dis[node];
    float4 b = *(const float4*)(b2 + l * 4);
    float4 r;
    r.x = fmaf(di, acc.x, b.x);
    r.y = fmaf(di, acc.y, b.y);
    r.z = fmaf(di, acc.z, b.z);
    r.w = fmaf(di, acc.w, b.w);
    *(float4*)(out + (size_t)node * COUT + l * 4) = r;
}

// ---------------------------------------------------------------------------
extern "C" void kernel_launch(void* const* d_in, const int* in_sizes, int n_in,
                              void* d_out, int out_size) {
    const float* x  = (const float*)d_in[0];
    const float* W1 = (const float*)d_in[1];
    const float* b1 = (const float*)d_in[2];
    const float* W2 = (const float*)d_in[3];
    const float* b2 = (const float*)d_in[4];
    const int* edge = (const int*)d_in[5];

    const int n = in_sizes[0] / CIN;
    const int e = in_sizes[5] / 2;
    const int* src = edge;
    const int* dst = edge + e;
    float* out = (float*)d_out;

    float *p_h1s = nullptr, *p_h = nullptr, *p_h2s = nullptr;
    cudaGetSymbolAddress((void**)&p_h1s, g_h1s);
    cudaGetSymbolAddress((void**)&p_h, g_h);
    cudaGetSymbolAddress((void**)&p_h2s, g_h2s);

    // GEMM1: CO=128, ROWS=96, NT=192 -> smem 112 KB (2 CTAs/SM)
    // GEMM2: CO=64,  ROWS=128, NT=128 -> smem 96 KB (2 CTAs/SM)
    const int smem1 = (128 * 128 + 96 * 128) * sizeof(float);
    const int smem2 = (128 * 64 + 128 * 128) * sizeof(float);
    cudaFuncSetAttribute(k_gemm8<128, 96, 192>, cudaFuncAttributeMaxDynamicSharedMemorySize, smem1);
    cudaFuncSetAttribute(k_gemm8<64, 128, 128>, cudaFuncAttributeMaxDynamicSharedMemorySize, smem2);

    const int nblk = (n + SCAN_B - 1) / SCAN_B;

    // CSR build + normalization
    k_zero<<<(n + 255) / 256, 256>>>(n);
    k_hist<<<(e + 255) / 256, 256>>>(dst, e);
    k_scan1<<<nblk, SCAN_B>>>(n);
    k_scan2<<<1, SCAN_B>>>(nblk);
    k_scan3<<<nblk, SCAN_B>>>(n);
    k_dis<<<(n + 255) / 256, 256>>>(n);
    k_scatter<<<(e + 255) / 256, 256>>>(src, dst, e);

    // layer 1
    k_gemm8<128, 96, 192><<<(n + 95) / 96, 192, smem1>>>(x, W1, 128, p_h1s, n);
    k_aggA<<<(int)(((size_t)n * 32 + 255) / 256), 256>>>(b1, n);

    // layer 2 (GEMM first: aggregate only 40 channels)
    k_gemm8<64, 128, 128><<<(n + 127) / 128, 128, smem2>>>(p_h, W2, COUT, p_h2s, n);
    k_aggB<<<(int)(((size_t)n * 10 + 319) / 320), 320>>>(b2, out, n);
}

// round 6
// speedup vs baseline: 3.0596x; 1.5116x over previous
#include <cuda_runtime.h>
#include <cuda_bf16.h>
#include <cstdint>

// Problem constants (N=170000, E=1200000, IN=HID=128, OUT=40)
#define NN 170000
#define EE 1200000
#define CIN 128
#define CH 128
#define COUT 40
#define SCAN_B 512
#define NBLK ((NN + SCAN_B - 1) / SCAN_B)   // 333
#define KS 136   // smem k-stride (bf16 elems), padded for bank-conflict-free LDSM

// Scratch (static __device__ arrays per allocation rules)
__device__ float g_h1s[(size_t)NN * CH];    // dis * (x @ W1)
__device__ float g_h[(size_t)NN * CH];      // relu'd hidden (layer-2 input)
__device__ float g_h2s[(size_t)NN * COUT];  // dis * (h @ W2)
__device__ float g_dis[NN];
__device__ int g_cnt[NN];    // in-degree histogram (excl. self-loop)
__device__ int g_incl[NN];   // inclusive prefix sum of g_cnt
__device__ int g_cur[NN];    // scatter cursor
__device__ int g_bsum[NBLK];
__device__ int g_boff[NBLK];
__device__ int g_csrc[EE];   // edge srcs grouped by dst

// ---------------------------------------------------------------------------
// CSR build: zero, histogram, 2-level scan, scatter
__global__ void k_zero(int n) {
    int i = blockIdx.x * blockDim.x + threadIdx.x;
    if (i < n) { g_cnt[i] = 0; g_cur[i] = 0; }
}

__global__ void k_hist(const int* __restrict__ dst, int e) {
    int i = blockIdx.x * blockDim.x + threadIdx.x;
    if (i < e) atomicAdd(&g_cnt[dst[i]], 1);
}

__global__ void k_scan1(int n) {
    __shared__ int sm[SCAN_B];
    int t = threadIdx.x;
    int i = blockIdx.x * SCAN_B + t;
    int v = (i < n) ? g_cnt[i] : 0;
    sm[t] = v;
    __syncthreads();
#pragma unroll
    for (int off = 1; off < SCAN_B; off <<= 1) {
        int u = (t >= off) ? sm[t - off] : 0;
        __syncthreads();
        sm[t] += u;
        __syncthreads();
    }
    if (i < n) g_incl[i] = sm[t];
    if (t == SCAN_B - 1) g_bsum[blockIdx.x] = sm[t];
}

__global__ void k_scan2(int nblk) {
    __shared__ int sm[SCAN_B];
    int t = threadIdx.x;
    int v = (t < nblk) ? g_bsum[t] : 0;
    sm[t] = v;
    __syncthreads();
#pragma unroll
    for (int off = 1; off < SCAN_B; off <<= 1) {
        int u = (t >= off) ? sm[t - off] : 0;
        __syncthreads();
        sm[t] += u;
        __syncthreads();
    }
    if (t < nblk) g_boff[t] = sm[t] - v;  // exclusive
}

// scan finalize + fused deg^{-1/2}
__global__ void k_scan3(int n) {
    int i = blockIdx.x * SCAN_B + threadIdx.x;
    if (i < n) {
        g_incl[i] += g_boff[blockIdx.x];
        g_dis[i] = rsqrtf((float)(g_cnt[i] + 1));  // +1 self-loop
    }
}

__global__ void k_scatter(const int* __restrict__ src, const int* __restrict__ dst, int e) {
    int i = blockIdx.x * blockDim.x + threadIdx.x;
    if (i >= e) return;
    int d = dst[i];
    int pos = atomicAdd(&g_cur[d], 1);
    g_csrc[g_incl[d] - g_cnt[d] + pos] = src[i];
}

// ---------------------------------------------------------------------------
// bf16-split tensor-core GEMM: Y[row,:] = dis[row] * (X[row,:128] @ W[:128,wcols])
// fp32 operands split v = hi + lo (bf16); 3 products hi*hi + hi*lo + lo*hi.
// CTA: 256 threads = 8 warps, layout 2(M) x 4(N). M-tile 64, N-tile CO.
// Warp tile: 32 x (CO/4). K=128 fully resident in smem.
__device__ __forceinline__ void ldsm_x4(uint32_t* r, uint32_t addr) {
    asm volatile("ldmatrix.sync.aligned.m8n8.x4.shared.b16 {%0,%1,%2,%3}, [%4];"
                 : "=r"(r[0]), "=r"(r[1]), "=r"(r[2]), "=r"(r[3]) : "r"(addr));
}
__device__ __forceinline__ void ldsm_x2(uint32_t* r, uint32_t addr) {
    asm volatile("ldmatrix.sync.aligned.m8n8.x2.shared.b16 {%0,%1}, [%2];"
                 : "=r"(r[0]), "=r"(r[1]) : "r"(addr));
}
__device__ __forceinline__ void mma_bf16(float* d, const uint32_t* a, const uint32_t* b) {
    asm volatile("mma.sync.aligned.m16n8k16.row.col.f32.bf16.bf16.f32 "
                 "{%0,%1,%2,%3}, {%4,%5,%6,%7}, {%8,%9}, {%0,%1,%2,%3};"
                 : "+f"(d[0]), "+f"(d[1]), "+f"(d[2]), "+f"(d[3])
                 : "r"(a[0]), "r"(a[1]), "r"(a[2]), "r"(a[3]), "r"(b[0]), "r"(b[1]));
}

template <int CO>
__global__ void __launch_bounds__(256, 2)
k_mma(const float* __restrict__ X, const float* __restrict__ Wg, int wcols,
      float* __restrict__ Y, int n) {
    extern __shared__ char smc[];
    __nv_bfloat16* Ahi = (__nv_bfloat16*)smc;              // 64*KS
    __nv_bfloat16* Alo = Ahi + 64 * KS;                    // 64*KS
    __nv_bfloat16* Whi = Alo + 64 * KS;                    // CO*KS
    __nv_bfloat16* Wlo = Whi + CO * KS;                    // CO*KS

    const int t = threadIdx.x;
    const int row0 = blockIdx.x * 64;

    // W transposed into smem: Whi/Wlo[nn][k], zero-padded for nn >= wcols
    for (int idx = t; idx < 128 * CO; idx += 256) {
        int k = idx / CO, nn_ = idx % CO;
        float v = (nn_ < wcols) ? Wg[k * wcols + nn_] : 0.f;
        __nv_bfloat16 h = __float2bfloat16(v);
        __nv_bfloat16 l = __float2bfloat16(v - __bfloat162float(h));
        Whi[nn_ * KS + k] = h;
        Wlo[nn_ * KS + k] = l;
    }
    // X tile [64][128] fp32 -> bf16 hi/lo (zero-fill tail rows)
    for (int idx = t; idx < 64 * 32; idx += 256) {
        int r = idx >> 5, c4 = idx & 31;
        float4 v = make_float4(0.f, 0.f, 0.f, 0.f);
        if (row0 + r < n) v = ((const float4*)(X + (size_t)(row0 + r) * 128))[c4];
        int k = c4 * 4;
        __nv_bfloat16 h0 = __float2bfloat16(v.x), h1 = __float2bfloat16(v.y);
        __nv_bfloat16 h2 = __float2bfloat16(v.z), h3 = __float2bfloat16(v.w);
        __nv_bfloat16 l0 = __float2bfloat16(v.x - __bfloat162float(h0));
        __nv_bfloat16 l1 = __float2bfloat16(v.y - __bfloat162float(h1));
        __nv_bfloat16 l2 = __float2bfloat16(v.z - __bfloat162float(h2));
        __nv_bfloat16 l3 = __float2bfloat16(v.w - __bfloat162float(h3));
        *(__nv_bfloat162*)(Ahi + r * KS + k)     = __halves2bfloat162(h0, h1);
        *(__nv_bfloat162*)(Ahi + r * KS + k + 2) = __halves2bfloat162(h2, h3);
        *(__nv_bfloat162*)(Alo + r * KS + k)     = __halves2bfloat162(l0, l1);
        *(__nv_bfloat162*)(Alo + r * KS + k + 2) = __halves2bfloat162(l2, l3);
    }
    __syncthreads();

    const int w = t >> 5, lane = t & 31;
    const int wm = w & 1, wn = w >> 1;          // 2(M) x 4(N)
    constexpr int NF = CO / 32;                 // n-frags per warp (4 or 2)
    constexpr int WN = CO / 4;                  // warp n-extent

    uint32_t sbase;
    asm("{ .reg .u64 tt; cvta.to.shared.u64 tt, %1; cvt.u32.u64 %0, tt; }"
        : "=r"(sbase) : "l"(smc));
    const uint32_t aHiB = sbase;
    const uint32_t aLoB = sbase + 64 * KS * 2;
    const uint32_t wHiB = sbase + 2 * 64 * KS * 2;
    const uint32_t wLoB = wHiB + CO * KS * 2;

    // per-lane invariant byte offsets
    uint32_t aOff[2];
#pragma unroll
    for (int mf = 0; mf < 2; mf++) {
        int row = wm * 32 + mf * 16 + (lane & 15);
        aOff[mf] = (uint32_t)(row * KS + ((lane >> 4) << 3)) * 2;
    }
    uint32_t bOff[NF];
#pragma unroll
    for (int nf = 0; nf < NF; nf++) {
        int nr = wn * WN + nf * 8 + (lane & 7);
        bOff[nf] = (uint32_t)(nr * KS + (lane & 8)) * 2;
    }

    float acc[2][NF][4];
#pragma unroll
    for (int mf = 0; mf < 2; mf++)
#pragma unroll
        for (int nf = 0; nf < NF; nf++)
#pragma unroll
            for (int i = 0; i < 4; i++) acc[mf][nf][i] = 0.f;

#pragma unroll
    for (int ks = 0; ks < 8; ks++) {
        const uint32_t kb = ks * 16 * 2;
        uint32_t ah[2][4], al[2][4], bh[NF][2], bl[NF][2];
#pragma unroll
        for (int mf = 0; mf < 2; mf++) {
            ldsm_x4(ah[mf], aHiB + aOff[mf] + kb);
            ldsm_x4(al[mf], aLoB + aOff[mf] + kb);
        }
#pragma unroll
        for (int nf = 0; nf < NF; nf++) {
            ldsm_x2(bh[nf], wHiB + bOff[nf] + kb);
            ldsm_x2(bl[nf], wLoB + bOff[nf] + kb);
        }
#pragma unroll
        for (int mf = 0; mf < 2; mf++)
#pragma unroll
            for (int nf = 0; nf < NF; nf++) {
                mma_bf16(acc[mf][nf], ah[mf], bh[nf]);
                mma_bf16(acc[mf][nf], ah[mf], bl[nf]);
                mma_bf16(acc[mf][nf], al[mf], bh[nf]);
            }
    }

    // epilogue: scale rows by g_dis, store
#pragma unroll
    for (int mf = 0; mf < 2; mf++) {
        int rowA = row0 + wm * 32 + mf * 16 + (lane >> 2);
        int rowB = rowA + 8;
        float dA = (rowA < n) ? g_dis[rowA] : 0.f;
        float dB = (rowB < n) ? g_dis[rowB] : 0.f;
#pragma unroll
        for (int nf = 0; nf < NF; nf++) {
            int col = wn * WN + nf * 8 + ((lane & 3) << 1);
            if (CO != 128 && col >= wcols) continue;  // GEMM2 pad cols
            if (rowA < n) {
                float2 v = make_float2(acc[mf][nf][0] * dA, acc[mf][nf][1] * dA);
                *(float2*)(Y + (size_t)rowA * wcols + col) = v;
            }
            if (rowB < n) {
                float2 v = make_float2(acc[mf][nf][2] * dB, acc[mf][nf][3] * dB);
                *(float2*)(Y + (size_t)rowB * wcols + col) = v;
            }
        }
    }
}

// ---------------------------------------------------------------------------
// Layer-1 aggregation, CSR gather, fused self-loop+bias+relu. Warp per node.
__global__ void k_aggA(const float* __restrict__ b1, int n) {
    int g = blockIdx.x * blockDim.x + threadIdx.x;
    int node = g >> 5, lane = g & 31;
    if (node >= n) return;
    int end = g_incl[node];
    int p = end - g_cnt[node];
    float4 acc = make_float4(0.f, 0.f, 0.f, 0.f);
    for (; p + 4 <= end; p += 4) {
        int s0 = g_csrc[p], s1 = g_csrc[p + 1], s2 = g_csrc[p + 2], s3 = g_csrc[p + 3];
        float4 v0 = ((const float4*)(g_h1s + (size_t)s0 * CH))[lane];
        float4 v1 = ((const float4*)(g_h1s + (size_t)s1 * CH))[lane];
        float4 v2 = ((const float4*)(g_h1s + (size_t)s2 * CH))[lane];
        float4 v3 = ((const float4*)(g_h1s + (size_t)s3 * CH))[lane];
        acc.x += (v0.x + v1.x) + (v2.x + v3.x);
        acc.y += (v0.y + v1.y) + (v2.y + v3.y);
        acc.z += (v0.z + v1.z) + (v2.z + v3.z);
        acc.w += (v0.w + v1.w) + (v2.w + v3.w);
    }
    for (; p < end; ++p) {
        int s = g_csrc[p];
        float4 v = ((const float4*)(g_h1s + (size_t)s * CH))[lane];
        acc.x += v.x; acc.y += v.y; acc.z += v.z; acc.w += v.w;
    }
    float4 hs = ((const float4*)(g_h1s + (size_t)node * CH))[lane];
    acc.x += hs.x; acc.y += hs.y; acc.z += hs.z; acc.w += hs.w;
    float di = g_dis[node];
    float4 b = ((const float4*)b1)[lane];
    float4 r;
    r.x = fmaxf(fmaf(di, acc.x, b.x), 0.f);
    r.y = fmaxf(fmaf(di, acc.y, b.y), 0.f);
    r.z = fmaxf(fmaf(di, acc.z, b.z), 0.f);
    r.w = fmaxf(fmaf(di, acc.w, b.w), 0.f);
    ((float4*)(g_h + (size_t)node * CH))[lane] = r;
}

// Layer-2 aggregation, CSR gather, fused self-loop+bias. 10 threads/node x 4ch.
__global__ void k_aggB(const float* __restrict__ b2, float* __restrict__ out, int n) {
    int g = blockIdx.x * blockDim.x + threadIdx.x;
    int node = g / 10, l = g % 10;
    if (node >= n) return;
    int end = g_incl[node];
    int p = end - g_cnt[node];
    float4 acc = make_float4(0.f, 0.f, 0.f, 0.f);
    for (; p + 4 <= end; p += 4) {
        int s0 = g_csrc[p], s1 = g_csrc[p + 1], s2 = g_csrc[p + 2], s3 = g_csrc[p + 3];
        float4 v0 = *(const float4*)(g_h2s + (size_t)s0 * COUT + l * 4);
        float4 v1 = *(const float4*)(g_h2s + (size_t)s1 * COUT + l * 4);
        float4 v2 = *(const float4*)(g_h2s + (size_t)s2 * COUT + l * 4);
        float4 v3 = *(const float4*)(g_h2s + (size_t)s3 * COUT + l * 4);
        acc.x += (v0.x + v1.x) + (v2.x + v3.x);
        acc.y += (v0.y + v1.y) + (v2.y + v3.y);
        acc.z += (v0.z + v1.z) + (v2.z + v3.z);
        acc.w += (v0.w + v1.w) + (v2.w + v3.w);
    }
    for (; p < end; ++p) {
        int s = g_csrc[p];
        float4 v = *(const float4*)(g_h2s + (size_t)s * COUT + l * 4);
        acc.x += v.x; acc.y += v.y; acc.z += v.z; acc.w += v.w;
    }
    float4 hs = *(const float4*)(g_h2s + (size_t)node * COUT + l * 4);
    acc.x += hs.x; acc.y += hs.y; acc.z += hs.z; acc.w += hs.w;
    float di = g_dis[node];
    float4 b = *(const float4*)(b2 + l * 4);
    float4 r;
    r.x = fmaf(di, acc.x, b.x);
    r.y = fmaf(di, acc.y, b.y);
    r.z = fmaf(di, acc.z, b.z);
    r.w = fmaf(di, acc.w, b.w);
    *(float4*)(out + (size_t)node * COUT + l * 4) = r;
}

// ---------------------------------------------------------------------------
extern "C" void kernel_launch(void* const* d_in, const int* in_sizes, int n_in,
                              void* d_out, int out_size) {
    const float* x  = (const float*)d_in[0];
    const float* W1 = (const float*)d_in[1];
    const float* b1 = (const float*)d_in[2];
    const float* W2 = (const float*)d_in[3];
    const float* b2 = (const float*)d_in[4];
    const int* edge = (const int*)d_in[5];

    const int n = in_sizes[0] / CIN;
    const int e = in_sizes[5] / 2;
    const int* src = edge;
    const int* dst = edge + e;
    float* out = (float*)d_out;

    float *p_h1s = nullptr, *p_h = nullptr, *p_h2s = nullptr;
    cudaGetSymbolAddress((void**)&p_h1s, g_h1s);
    cudaGetSymbolAddress((void**)&p_h, g_h);
    cudaGetSymbolAddress((void**)&p_h2s, g_h2s);

    // smem: A (2 levels) + W (2 levels)
    const int smem1 = (2 * 64 * KS + 2 * 128 * KS) * 2;  // 104448 B
    const int smem2 = (2 * 64 * KS + 2 * 64 * KS) * 2;   // 69632 B
    cudaFuncSetAttribute(k_mma<128>, cudaFuncAttributeMaxDynamicSharedMemorySize, smem1);
    cudaFuncSetAttribute(k_mma<64>,  cudaFuncAttributeMaxDynamicSharedMemorySize, smem2);

    const int nblk = (n + SCAN_B - 1) / SCAN_B;

    // CSR build + normalization
    k_zero<<<(n + 255) / 256, 256>>>(n);
    k_hist<<<(e + 255) / 256, 256>>>(dst, e);
    k_scan1<<<nblk, SCAN_B>>>(n);
    k_scan2<<<1, SCAN_B>>>(nblk);
    k_scan3<<<nblk, SCAN_B>>>(n);
    k_scatter<<<(e + 255) / 256, 256>>>(src, dst, e);

    // layer 1
    k_mma<128><<<(n + 63) / 64, 256, smem1>>>(x, W1, 128, p_h1s, n);
    k_aggA<<<(int)(((size_t)n * 32 + 255) / 256), 256>>>(b1, n);

    // layer 2 (GEMM first: aggregate only 40 channels)
    k_mma<64><<<(n + 63) / 64, 256, smem2>>>(p_h, W2, COUT, p_h2s, n);
    k_aggB<<<(int)(((size_t)n * 10 + 319) / 320), 320>>>(b2, out, n);
}